// round 12
// baseline (speedup 1.0000x reference)
#include <cuda_runtime.h>
#include <math.h>

#define N_NODES_MAX 50000
#define D 64
#define N_REL 8

__device__ float g_agg[(size_t)N_NODES_MAX * D];   // 12.8 MB
__device__ float g_cnt[N_NODES_MAX];
__device__ float g_w[N_REL * 2 * D];               // w = W_r.sum(-1)
__device__ float g_y[(size_t)N_NODES_MAX * 16];    // y tables

// packed f32x2 helpers (FFMA2 is PTX-only; ptxas won't auto-fuse)
__device__ __forceinline__ unsigned long long pack2(float lo, float hi) {
    unsigned long long r;
    asm("mov.b64 %0, {%1,%2};" : "=l"(r) : "f"(lo), "f"(hi));
    return r;
}
__device__ __forceinline__ void unpack2(unsigned long long v, float& lo, float& hi) {
    asm("mov.b64 {%0,%1}, %2;" : "=f"(lo), "=f"(hi) : "l"(v));
}
#define FMA2(a, c, w) asm("fma.rn.f32x2 %0, %1, %2, %0;" : "+l"(a) : "l"(c), "l"(w))

// ---------------------------------------------------------------------------
// Kernel 1: w[r][j] = sum_k W_r[r][j][k]
// ---------------------------------------------------------------------------
__global__ void wsum_kernel(const float* __restrict__ W_r) {
    int r = blockIdx.x;
    int j = threadIdx.x;
    const float4* row = (const float4*)(W_r + ((size_t)r * 2 * D + j) * D);
    float4 s = make_float4(0.f, 0.f, 0.f, 0.f);
#pragma unroll
    for (int k = 0; k < D / 4; k++) {
        float4 v = __ldg(row + k);
        s.x += v.x; s.y += v.y; s.z += v.z; s.w += v.w;
    }
    g_w[r * 2 * D + j] = (s.x + s.y) + (s.z + s.w);
}

// ---------------------------------------------------------------------------
// Kernel 1b: y tables + fused scratch zeroing.
// ---------------------------------------------------------------------------
__global__ __launch_bounds__(256) void y_kernel(const float* __restrict__ x, int N) {
    __shared__ float xt[D][17];
    __shared__ float wt[D][16];

    int tid = threadIdx.x;
    int base = blockIdx.x * 16;

    {
        int gidx = blockIdx.x * blockDim.x + tid;
        int n_agg4 = N * (D / 4);
        int stride = gridDim.x * blockDim.x;
        for (int i = gidx; i < n_agg4; i += stride)
            ((float4*)g_agg)[i] = make_float4(0.f, 0.f, 0.f, 0.f);
        for (int i = gidx; i < N; i += stride)
            g_cnt[i] = 0.f;
    }

#pragma unroll
    for (int q = 0; q < 4; q++) {
        int idx = tid + q * 256;
        int k = idx >> 4, j = idx & 15;
        wt[k][j] = (j < 8) ? g_w[j * 2 * D + k] : g_w[(j - 8) * 2 * D + D + k];
    }
    {
        int n = tid >> 4;
        int k0 = (tid & 15) * 4;
        int nn = min(base + n, N - 1);
        float4 v = __ldg((const float4*)(x + (size_t)nn * D + k0));
        xt[k0 + 0][n] = v.x; xt[k0 + 1][n] = v.y;
        xt[k0 + 2][n] = v.z; xt[k0 + 3][n] = v.w;
    }
    __syncthreads();

    int n = tid & 15, j = tid >> 4;
    float acc = 0.f;
#pragma unroll
    for (int k = 0; k < D; k++) acc += xt[k][n] * wt[k][j];

    int nn = base + n;
    if (nn < N) g_y[(size_t)nn * 16 + j] = acc;
}

// ---------------------------------------------------------------------------
// Kernel 3: edge phase. One edge per lane; shuffle-broadcast gather + RED.
// ---------------------------------------------------------------------------
__global__ __launch_bounds__(256) void edge_kernel(
        const float* __restrict__ x,
        const int* __restrict__ src,
        const int* __restrict__ dst,
        const int* __restrict__ rel,
        int E) {
    int warp = (blockIdx.x * blockDim.x + threadIdx.x) >> 5;
    int lane = threadIdx.x & 31;

    int ew = warp * 32;
    if (ew >= E) return;
    int ne = min(32, E - ew);

    int e = ew + min(lane, ne - 1);
    int s = __ldg(src + e);
    int d = __ldg(dst + e);
    int r = __ldg(rel + e);

    float yd = __ldg(g_y + (size_t)d * 16 + r);
    float ys = __ldg(g_y + (size_t)s * 16 + 8 + r);
    float gate = 1.0f / (1.0f + __expf(-(yd + ys)));

    if (lane < ne) atomicAdd(g_cnt + d, 1.0f);

    const float2* x2 = (const float2*)x;
    int j = 0;
    for (; j + 4 <= ne; j += 4) {
        int s0 = __shfl_sync(0xffffffffu, s, j + 0);
        int s1 = __shfl_sync(0xffffffffu, s, j + 1);
        int s2 = __shfl_sync(0xffffffffu, s, j + 2);
        int s3 = __shfl_sync(0xffffffffu, s, j + 3);
        int d0 = __shfl_sync(0xffffffffu, d, j + 0);
        int d1 = __shfl_sync(0xffffffffu, d, j + 1);
        int d2 = __shfl_sync(0xffffffffu, d, j + 2);
        int d3 = __shfl_sync(0xffffffffu, d, j + 3);
        float g0 = __shfl_sync(0xffffffffu, gate, j + 0);
        float g1 = __shfl_sync(0xffffffffu, gate, j + 1);
        float g2 = __shfl_sync(0xffffffffu, gate, j + 2);
        float g3 = __shfl_sync(0xffffffffu, gate, j + 3);

        float2 v0 = __ldg(x2 + (size_t)s0 * (D / 2) + lane);
        float2 v1 = __ldg(x2 + (size_t)s1 * (D / 2) + lane);
        float2 v2 = __ldg(x2 + (size_t)s2 * (D / 2) + lane);
        float2 v3 = __ldg(x2 + (size_t)s3 * (D / 2) + lane);

        float* a0 = g_agg + (size_t)d0 * D + lane * 2;
        float* a1 = g_agg + (size_t)d1 * D + lane * 2;
        float* a2 = g_agg + (size_t)d2 * D + lane * 2;
        float* a3 = g_agg + (size_t)d3 * D + lane * 2;
        asm volatile("red.global.add.v2.f32 [%0], {%1,%2};"
                     :: "l"(a0), "f"(v0.x * g0), "f"(v0.y * g0) : "memory");
        asm volatile("red.global.add.v2.f32 [%0], {%1,%2};"
                     :: "l"(a1), "f"(v1.x * g1), "f"(v1.y * g1) : "memory");
        asm volatile("red.global.add.v2.f32 [%0], {%1,%2};"
                     :: "l"(a2), "f"(v2.x * g2), "f"(v2.y * g2) : "memory");
        asm volatile("red.global.add.v2.f32 [%0], {%1,%2};"
                     :: "l"(a3), "f"(v3.x * g3), "f"(v3.y * g3) : "memory");
    }
    for (; j < ne; j++) {
        int sj = __shfl_sync(0xffffffffu, s, j);
        int dj = __shfl_sync(0xffffffffu, d, j);
        float gj = __shfl_sync(0xffffffffu, gate, j);
        float2 v = __ldg(x2 + (size_t)sj * (D / 2) + lane);
        float* a = g_agg + (size_t)dj * D + lane * 2;
        asm volatile("red.global.add.v2.f32 [%0], {%1,%2};"
                     :: "l"(a), "f"(v.x * gj), "f"(v.y * gj) : "memory");
    }
}

// ---------------------------------------------------------------------------
// Kernel 4: node GEMM with packed FFMA2.
//   Block: 256 threads, 64 nodes x 64 outs. Thread: 2 nodes x 8 outs, with
//   outputs packed in f32x2 pairs -> 8 u64 accumulators.
//   wsm now K-MAJOR [k][o] (pad +4): one ulonglong2 broadcast load per k
//   gives 4 pre-packed (w_j, w_j+1) pairs for free.
//   csm [k][node] pad 66 unchanged; per k, 2 mov.b64 packs (c,c) per node.
// ---------------------------------------------------------------------------
#define BN 64
#define KCH 64

__global__ __launch_bounds__(256, 3) void node_kernel(
        const float* __restrict__ x,
        const float* __restrict__ Wl,   // [64][128]
        const float* __restrict__ b,    // [64]
        float* __restrict__ out,
        int N) {
    __shared__ float csm[KCH][66];      // 16.9 KB
    __shared__ float wsm[KCH][D + 4];   // 17.4 KB, k-major, 16B-aligned rows

    int tid = threadIdx.x;
    int tx = tid & 31;    // node pair
    int ty = tid >> 5;    // out group (8 outs = 4 packed pairs)
    int base = blockIdx.x * BN;

    // accumulators: [node][jpair], packed (out ty*8+2p, ty*8+2p+1)
    unsigned long long acc[2][4];
#pragma unroll
    for (int p = 0; p < 4; p++) {
        float b0 = __ldg(b + ty * 8 + 2 * p);
        float b1 = __ldg(b + ty * 8 + 2 * p + 1);
        unsigned long long bb = pack2(b0, b1);
        acc[0][p] = bb; acc[1][p] = bb;
    }

#pragma unroll
    for (int kc = 0; kc < 2; kc++) {
        // ---- stage weight chunk TRANSPOSED: wsm[k][o] = Wl[o][kc*64+k] ----
#pragma unroll
        for (int q = 0; q < 4; q++) {
            int idx = tid + q * 256;        // 0..1023
            int o = idx >> 4;               // 0..63
            int k0 = (idx & 15) * 4;        // 0..60
            float4 v = __ldg((const float4*)(Wl + (size_t)o * 2 * D + kc * KCH + k0));
            wsm[k0 + 0][o] = v.x;
            wsm[k0 + 1][o] = v.y;
            wsm[k0 + 2][o] = v.z;
            wsm[k0 + 3][o] = v.w;
        }
        // ---- stage combined chunk, transposed: csm[k][node] ----
        {
            int n = tid & 63;
            int q16 = tid >> 6;
            int k0 = q16 * 16;
            int nn = min(base + n, N - 1);
            const float4* srcp;
            float scale;
            if (kc == 0) {
                srcp = (const float4*)(x + (size_t)nn * D + k0);
                scale = 1.0f;
            } else {
                srcp = (const float4*)(g_agg + (size_t)nn * D + k0);
                scale = 1.0f / fmaxf(g_cnt[nn], 1.0f);
            }
#pragma unroll
            for (int q = 0; q < 4; q++) {
                float4 v = __ldg(srcp + q);
                int k = k0 + q * 4;
                csm[k + 0][n] = v.x * scale;
                csm[k + 1][n] = v.y * scale;
                csm[k + 2][n] = v.z * scale;
                csm[k + 3][n] = v.w * scale;
            }
        }
        __syncthreads();

        // ---- inner loop: per k, 2 broadcast LDS.128 (w pairs) + 1 LDS.64 (c)
        //      + 2 packs + 8 FFMA2 ----
#pragma unroll 8
        for (int k = 0; k < KCH; k++) {
            ulonglong2 wA = *(const ulonglong2*)&wsm[k][ty * 8];      // pairs 0,1
            ulonglong2 wB = *(const ulonglong2*)&wsm[k][ty * 8 + 4];  // pairs 2,3
            float2 c = *(const float2*)&csm[k][tx * 2];
            unsigned long long c0 = pack2(c.x, c.x);
            unsigned long long c1 = pack2(c.y, c.y);

            FMA2(acc[0][0], c0, wA.x);
            FMA2(acc[0][1], c0, wA.y);
            FMA2(acc[0][2], c0, wB.x);
            FMA2(acc[0][3], c0, wB.y);
            FMA2(acc[1][0], c1, wA.x);
            FMA2(acc[1][1], c1, wA.y);
            FMA2(acc[1][2], c1, wB.x);
            FMA2(acc[1][3], c1, wB.y);
        }
        __syncthreads();
    }

    // ---- epilogue: unpack, leaky relu, store ----
#pragma unroll
    for (int i = 0; i < 2; i++) {
        int n = base + tx * 2 + i;
        if (n < N) {
            float v[8];
#pragma unroll
            for (int p = 0; p < 4; p++)
                unpack2(acc[i][p], v[2 * p], v[2 * p + 1]);
#pragma unroll
            for (int q = 0; q < 8; q++)
                v[q] = v[q] > 0.f ? v[q] : 0.01f * v[q];
            float* op = out + (size_t)n * D + ty * 8;
            *(float4*)op = make_float4(v[0], v[1], v[2], v[3]);
            *(float4*)(op + 4) = make_float4(v[4], v[5], v[6], v[7]);
        }
    }
}

// ---------------------------------------------------------------------------
extern "C" void kernel_launch(void* const* d_in, const int* in_sizes, int n_in,
                              void* d_out, int out_size) {
    const float* x    = (const float*)d_in[0];
    const int*   src  = (const int*)d_in[1];
    const int*   dst  = (const int*)d_in[2];
    const int*   rel  = (const int*)d_in[3];
    const float* W_r  = (const float*)d_in[4];
    const float* W_lin= (const float*)d_in[5];
    const float* b_lin= (const float*)d_in[6];
    float* out = (float*)d_out;

    int N = in_sizes[0] / D;     // 50000
    int E = in_sizes[1];         // 800000

    wsum_kernel<<<N_REL, 2 * D>>>(W_r);

    y_kernel<<<(N + 15) / 16, 256>>>(x, N);

    int ewarps = (E + 31) / 32;
    edge_kernel<<<(ewarps * 32 + 255) / 256, 256>>>(x, src, dst, rel, E);

    node_kernel<<<(N + BN - 1) / BN, 256>>>(x, W_lin, b_lin, out, N);
}